// round 15
// baseline (speedup 1.0000x reference)
#include <cuda_runtime.h>
#include <cuda_fp16.h>
#include <cstdint>

#define CTXD   512
#define HIDD   2048
#define NCELLS 4096
#define NBATCH 8
#define KNN    8
#define MTOT   (NBATCH * NCELLS)   // 32768

__device__ __half g_aggh[(size_t)MTOT * CTXD];  // 32 MB fp16 agg
__device__ __half g_Wh[(size_t)HIDD * CTXD];    // 2 MB fp16 W^T
// [0]=tile ctr, [1]=w task ctr, [2]=agg task ctr, [3]=w done, [4+mb]=agg done
__device__ int    g_sync[4 + 256];

#define BM 128
#define BN 128
#define BK 64
#define NT (CTXD / BK)                        // 8
#define NTILES ((MTOT / BM) * (HIDD / BN))    // 4096 ; tile>>4 = m-block
#define SSTRIDE 72
#define TILE_H (128 * SSTRIDE)
#define STAGE_H (2 * TILE_H)                  // halves
#define GEMM_SMEM_H (3 * STAGE_H)             // halves
#define PREP_WARP_FLOATS 1056                 // 32x33 transpose tile
#define TOTAL_SMEM (GEMM_SMEM_H * 2 + 8 * PREP_WARP_FLOATS * 4)  // 144384 B

#define GRID_CTAS 152
#define N_W_TASKS 1024
#define N_AGG_TASKS 8192                      // 4 cells each
#define AGG_PER_MB 32

__device__ __forceinline__ void cpasync16(uint32_t saddr, const void* g) {
    asm volatile("cp.async.cg.shared.global [%0], [%1], 16;\n" :: "r"(saddr), "l"(g));
}
__device__ __forceinline__ void ldsm_x4(uint32_t& r0, uint32_t& r1,
                                        uint32_t& r2, uint32_t& r3, uint32_t a) {
    asm volatile("ldmatrix.sync.aligned.m8n8.x4.shared.b16 {%0,%1,%2,%3},[%4];"
                 : "=r"(r0), "=r"(r1), "=r"(r2), "=r"(r3) : "r"(a));
}
#define GEMM_BAR() asm volatile("bar.sync 1, 256;" ::: "memory")

// ---------------- prep: warp-level W transpose (32x32) ----------------
__device__ void wtrans_warp(int wb, const float* __restrict__ W,
                            float* buf, int lane) {
    const int bx = wb & 63;               // HIDD/32
    const int by = wb >> 6;               // CTXD/32
#pragma unroll
    for (int i = 0; i < 32; i++)
        buf[i * 33 + lane] = W[(size_t)(by * 32 + i) * HIDD + bx * 32 + lane];
    __syncwarp();
#pragma unroll
    for (int i = 0; i < 32; i++)
        g_Wh[(size_t)(bx * 32 + i) * CTXD + by * 32 + lane] =
            __float2half(buf[lane * 33 + i]);
    __syncwarp();
}

// ---------------- prep: warp-level agg of 4 cells (MLP 32) ----------------
__device__ void agg_warp(int task, const float* __restrict__ x,
                         const int* __restrict__ nn_idx,
                         const float* __restrict__ sim, int lane) {
    const int r0 = task * 4;              // global rows r0..r0+3
#pragma unroll 1
    for (int c = 0; c < 4; c++) {
        const int r = r0 + c;
        const int b = r >> 12;
        const int n = r & 4095;
        int   ki[KNN];
        float ks[KNN];
#pragma unroll
        for (int k = 0; k < KNN; k++) {
            ki[k] = __ldg(&nn_idx[n * KNN + k]);
            ks[k] = __ldg(&sim[n * KNN + k]);
        }
        const float2* xb = reinterpret_cast<const float2*>(x) +
                           (size_t)b * NCELLS * 256;
        uint32_t* dst = reinterpret_cast<uint32_t*>(g_aggh) + (size_t)r * 256;
#pragma unroll
        for (int h = 0; h < 2; h++) {
            float2 v[KNN][4];
#pragma unroll
            for (int k = 0; k < KNN; k++)
#pragma unroll
                for (int j = 0; j < 4; j++)
                    v[k][j] = xb[(size_t)ki[k] * 256 + h * 128 + j * 32 + lane];
#pragma unroll
            for (int j = 0; j < 4; j++) {
                float ax = 0.f, ay = 0.f;
#pragma unroll
                for (int k = 0; k < KNN; k++) {
                    ax = fmaf(ks[k], v[k][j].x, ax);
                    ay = fmaf(ks[k], v[k][j].y, ay);
                }
                __half2 hh = __float22half2_rn(make_float2(ax, ay));
                dst[h * 128 + j * 32 + lane] = *reinterpret_cast<uint32_t*>(&hh);
            }
        }
    }
}

__device__ __forceinline__ void wait_ge(volatile int* p, int v) {
    while (atomicAdd((int*)p, 0) < v) __nanosleep(128);
}

// ---------------------------------------------------------------------------
// Fused kernel: warps 0-7 persistent GEMM (R9/R12 core, named barrier),
// warps 8-15 prep producers (then retire). 1 CTA/SM.
// ---------------------------------------------------------------------------
__global__ __launch_bounds__(512, 1) void fused_kernel(
    const float* __restrict__ x,
    const float* __restrict__ W,
    const int*   __restrict__ nn_idx,
    const float* __restrict__ sim,
    float*       __restrict__ C)
{
    extern __shared__ __half sm[];
    __shared__ int sm_next;

    const int tid  = threadIdx.x;
    const int lane = tid & 31;
    const int warp = tid >> 5;

    // ===================== producer warps =====================
    if (warp >= 8) {
        float* buf = reinterpret_cast<float*>(sm + GEMM_SMEM_H) +
                     (warp - 8) * PREP_WARP_FLOATS;
        // W transpose tasks
        while (true) {
            int t_;
            if (lane == 0) t_ = atomicAdd(&g_sync[1], 1);
            t_ = __shfl_sync(0xffffffff, t_, 0);
            if (t_ >= N_W_TASKS) break;
            wtrans_warp(t_, W, buf, lane);
            __threadfence();
            __syncwarp();
            if (lane == 0) atomicAdd(&g_sync[3], 1);
        }
        // agg tasks (ascending -> m-blocks delivered in order)
        while (true) {
            int t_;
            if (lane == 0) t_ = atomicAdd(&g_sync[2], 1);
            t_ = __shfl_sync(0xffffffff, t_, 0);
            if (t_ >= N_AGG_TASKS) break;
            agg_warp(t_, x, nn_idx, sim, lane);
            __threadfence();
            __syncwarp();
            if (lane == 0) atomicAdd(&g_sync[4 + (t_ >> 5)], 1);
        }
        return;   // retire producer warps
    }

    // ===================== GEMM warps (0..7) =====================
    const __half* A = g_aggh;
    const __half* B = g_Wh;
    const int wm = warp & 3;      // 32-row quarter
    const int wn = warp >> 2;     // 64-col half
    const int g  = lane >> 2;
    const int t4 = lane & 3;

    auto load_chunk = [&](int buf, int tile, int kt) {
        const int m0 = (tile >> 4) * BM;
        const int n0 = (tile & 15) * BN;
        __half* Asb = sm + buf * STAGE_H;
        __half* Bsb = Asb + TILE_H;
        const __half* Ag = A + (size_t)m0 * CTXD + kt * BK;
        const __half* Bg = B + (size_t)n0 * CTXD + kt * BK;
#pragma unroll
        for (int i = 0; i < 4; i++) {
            int idx = i * 256 + tid;
            int row = idx >> 3;
            int c8  = (idx & 7) * 8;
            cpasync16((uint32_t)__cvta_generic_to_shared(Asb + row * SSTRIDE + c8),
                      Ag + (size_t)row * CTXD + c8);
        }
#pragma unroll
        for (int i = 0; i < 4; i++) {
            int idx = i * 256 + tid;
            int row = idx >> 3;
            int c8  = (idx & 7) * 8;
            cpasync16((uint32_t)__cvta_generic_to_shared(Bsb + row * SSTRIDE + c8),
                      Bg + (size_t)row * CTXD + c8);
        }
        asm volatile("cp.async.commit_group;\n");
    };

    // first tile: acquire + wait for W and its m-block
    if (tid == 0) {
        int tl = atomicAdd(&g_sync[0], 1);
        if (tl < NTILES) {
            wait_ge(&g_sync[3], N_W_TASKS);
            wait_ge(&g_sync[4 + (tl >> 4)], AGG_PER_MB);
            __threadfence();
        }
        sm_next = tl;
    }
    GEMM_BAR();
    int tile = sm_next;
    if (tile >= NTILES) return;

    load_chunk(0, tile, 0);
    load_chunk(1, tile, 1);
    int st = 0;
    int ahead = 1;

    const int a_r  = lane & 15;
    const int a_k  = (lane >> 4) * 8;
    const int b_r  = lane & 7;
    const int b_no = ((lane >> 3) >> 1) * 8;
    const int b_ko = ((lane >> 3) & 1) * 8;

    while (true) {
        float acc[2][8][4];
#pragma unroll
        for (int i = 0; i < 2; i++)
#pragma unroll
            for (int j = 0; j < 8; j++)
#pragma unroll
                for (int r = 0; r < 4; r++) acc[i][j][r] = 0.f;

        int next_tile = NTILES;

        for (int kt = 0; kt < NT; ++kt) {
            if (ahead > 0) asm volatile("cp.async.wait_group 1;\n");
            else           asm volatile("cp.async.wait_group 0;\n");
            GEMM_BAR();

            if (kt == NT - 3) {
                if (tid == 0) {
                    int nt = atomicAdd(&g_sync[0], 1);
                    if (nt < NTILES) {
                        wait_ge(&g_sync[4 + (nt >> 4)], AGG_PER_MB);
                        __threadfence();
                    }
                    sm_next = nt;
                }
            }
            if (kt == NT - 2) next_tile = sm_next;

            if (kt + 2 < NT) {
                load_chunk((st + 2) % 3, tile, kt + 2);
                ahead = 2;
            } else if (next_tile < NTILES) {
                load_chunk((st + 2) % 3, next_tile, kt + 2 - NT);
                ahead = 2;
            }

            const __half* Asb = sm + st * STAGE_H;
            const __half* Bsb = Asb + TILE_H;

#pragma unroll
            for (int ks = 0; ks < 4; ++ks) {
                const int k0 = ks * 16;

                uint32_t af[2][4];
#pragma unroll
                for (int mi = 0; mi < 2; ++mi) {
                    uint32_t a = (uint32_t)__cvta_generic_to_shared(
                        Asb + (wm * 32 + mi * 16 + a_r) * SSTRIDE + k0 + a_k);
                    ldsm_x4(af[mi][0], af[mi][1], af[mi][2], af[mi][3], a);
                }
                uint32_t bf[8][2];
#pragma unroll
                for (int nj = 0; nj < 4; ++nj) {
                    uint32_t a = (uint32_t)__cvta_generic_to_shared(
                        Bsb + (wn * 64 + nj * 16 + b_no + b_r) * SSTRIDE + k0 + b_ko);
                    ldsm_x4(bf[2 * nj][0], bf[2 * nj][1],
                            bf[2 * nj + 1][0], bf[2 * nj + 1][1], a);
                }
#pragma unroll
                for (int mi = 0; mi < 2; ++mi)
#pragma unroll
                    for (int ni = 0; ni < 8; ++ni) {
                        asm volatile(
                            "mma.sync.aligned.m16n8k16.row.col.f32.f16.f16.f32 "
                            "{%0,%1,%2,%3},{%4,%5,%6,%7},{%8,%9},{%0,%1,%2,%3};\n"
                            : "+f"(acc[mi][ni][0]), "+f"(acc[mi][ni][1]),
                              "+f"(acc[mi][ni][2]), "+f"(acc[mi][ni][3])
                            : "r"(af[mi][0]), "r"(af[mi][1]),
                              "r"(af[mi][2]), "r"(af[mi][3]),
                              "r"(bf[ni][0]), "r"(bf[ni][1]));
                    }
            }
            GEMM_BAR();
            st = (st + 1) % 3;
            ahead -= 1;
        }

        // epilogue
        {
            const int m0 = (tile >> 4) * BM;
            const int n0 = (tile & 15) * BN;
#pragma unroll
            for (int mi = 0; mi < 2; ++mi) {
#pragma unroll
                for (int ni = 0; ni < 8; ++ni) {
                    const int r = m0 + wm * 32 + mi * 16 + g;
                    const int c = n0 + wn * 64 + ni * 8 + t4 * 2;
                    float2 v0 = make_float2(acc[mi][ni][0], acc[mi][ni][1]);
                    float2 v1 = make_float2(acc[mi][ni][2], acc[mi][ni][3]);
                    *reinterpret_cast<float2*>(C + (size_t)r * HIDD + c)       = v0;
                    *reinterpret_cast<float2*>(C + (size_t)(r + 8) * HIDD + c) = v1;
                }
            }
        }

        if (next_tile >= NTILES) break;
        tile = next_tile;
    }
}

// ---------------------------------------------------------------------------
extern "C" void kernel_launch(void* const* d_in, const int* in_sizes, int n_in,
                              void* d_out, int out_size) {
    const float* x      = (const float*)d_in[0];
    const float* W      = (const float*)d_in[1];
    const int*   nn_idx = (const int*)  d_in[2];
    const float* sim    = (const float*)d_in[3];
    float*       out    = (float*)d_out;

    int* syncp = nullptr;
    cudaGetSymbolAddress((void**)&syncp, g_sync);

    cudaFuncSetAttribute(fused_kernel,
                         cudaFuncAttributeMaxDynamicSharedMemorySize, TOTAL_SMEM);

    cudaMemsetAsync(syncp, 0, sizeof(int) * (4 + 256));
    fused_kernel<<<GRID_CTAS, 512, TOTAL_SMEM>>>(x, W, nn_idx, sim, out);
}

// round 16
// speedup vs baseline: 1.2469x; 1.2469x over previous
#include <cuda_runtime.h>
#include <cuda_fp16.h>
#include <cstdint>

// Problem constants
#define CTXD   512
#define HIDD   2048
#define NCELLS 4096      // 64*64
#define NBATCH 8
#define KNN    8
#define MTOT   (NBATCH * NCELLS)   // 32768

// Scratch (allowed: __device__ globals)
__device__ __half g_aggh[(size_t)MTOT * CTXD];  // 32 MB fp16 agg
__device__ __half g_Wh[(size_t)HIDD * CTXD];    // 2 MB  fp16 W^T

// ---------------------------------------------------------------------------
// Kernel 1: fused prep, 256 threads.
//   blocks [0,4096):    agg over 2x4 cell patches (8 cells, L1-reuse)
//   blocks [4096,5120): W transpose -> fp16 (32x32 tiles)
// ---------------------------------------------------------------------------
#define AGG_BLOCKS 4096
#define PREP_BLOCKS (AGG_BLOCKS + 1024)

__global__ __launch_bounds__(256) void prep_kernel(
    const float* __restrict__ x,
    const int*   __restrict__ nn_idx,
    const float* __restrict__ sim,
    const float* __restrict__ W)
{
    const int bid = blockIdx.x;
    const int t   = threadIdx.x;

    if (bid < AGG_BLOCKS) {
        // ---- agg: 2x4 patch of cells, 2 cells in flight ----
        const int b  = bid >> 9;            // batch (512 patches per batch)
        const int p  = bid & 511;
        const int pr = (p >> 4) * 2;        // patch row origin (0..62)
        const int pc = (p & 15) * 4;        // patch col origin (0..60)

        __shared__ int   s_idx[8 * KNN];
        __shared__ float s_sim[8 * KNN];
        if (t < 8 * KNN) {
            const int cell = t >> 3;        // 0..7
            const int k    = t & 7;
            const int n    = (pr + (cell >> 2)) * 64 + pc + (cell & 3);
            s_idx[t] = nn_idx[n * KNN + k];
            s_sim[t] = sim[n * KNN + k];
        }
        __syncthreads();

        const int lane = t & 127;           // float4 lane
        const int sub  = t >> 7;            // 0/1

        const float4* xb = reinterpret_cast<const float4*>(x) +
                           (size_t)b * NCELLS * (CTXD / 4);
        uint2* dst = reinterpret_cast<uint2*>(g_aggh);

#pragma unroll
        for (int c = 0; c < 4; c++) {
            const int ci = c * 2 + sub;                         // 0..7
            const int n  = (pr + (ci >> 2)) * 64 + pc + (ci & 3);
            float4 acc = make_float4(0.f, 0.f, 0.f, 0.f);
#pragma unroll
            for (int k = 0; k < KNN; k++) {
                const float  s = s_sim[ci * KNN + k];
                const float4 v = xb[(size_t)s_idx[ci * KNN + k] * (CTXD / 4) + lane];
                acc.x = fmaf(s, v.x, acc.x);
                acc.y = fmaf(s, v.y, acc.y);
                acc.z = fmaf(s, v.z, acc.z);
                acc.w = fmaf(s, v.w, acc.w);
            }
            __half2 h0 = __float22half2_rn(make_float2(acc.x, acc.y));
            __half2 h1 = __float22half2_rn(make_float2(acc.z, acc.w));
            uint2 pk;
            pk.x = *reinterpret_cast<uint32_t*>(&h0);
            pk.y = *reinterpret_cast<uint32_t*>(&h1);
            dst[((size_t)b * NCELLS + n) * (CTXD / 4) + lane] = pk;
        }
    } else {
        // ---- wtrans: Wt[n][k] = (half)W[k][n], 32x32 tile ----
        const int wb = bid - AGG_BLOCKS;     // 0..1023
        const int bx = wb & 63;              // HIDD/32
        const int by = wb >> 6;              // CTXD/32
        const int tx = t & 31;
        const int ty = t >> 5;               // 0..7

        __shared__ float tile[32][33];
#pragma unroll
        for (int i = 0; i < 4; i++)
            tile[ty + i * 8][tx] =
                W[(size_t)(by * 32 + ty + i * 8) * HIDD + bx * 32 + tx];
        __syncthreads();
#pragma unroll
        for (int i = 0; i < 4; i++)
            g_Wh[(size_t)(bx * 32 + ty + i * 8) * CTXD + by * 32 + tx] =
                __float2half(tile[tx][ty + i * 8]);
    }
}

// ---------------------------------------------------------------------------
// Kernel 2: fp16 mma.sync GEMM (R9 proven, untouched). 128x128 CTA tile,
// 8 warps (warp tile 32x64), BK=64, 3-stage cp.async, ldmatrix, fp32 accum,
// 2 CTA/SM.
// ---------------------------------------------------------------------------
#define BM 128
#define BN 128
#define BK 64
#define NT (CTXD / BK)         // 8 k-chunks
#define SSTRIDE 72             // BK + 8 pad (halves)
#define TILE_H (128 * SSTRIDE)
#define STAGE_H (2 * TILE_H)
#define GEMM_SMEM (3 * STAGE_H * 2)   // 110592 bytes

__device__ __forceinline__ void cpasync16(uint32_t saddr, const void* g) {
    asm volatile("cp.async.cg.shared.global [%0], [%1], 16;\n" :: "r"(saddr), "l"(g));
}
__device__ __forceinline__ void ldsm_x4(uint32_t& r0, uint32_t& r1,
                                        uint32_t& r2, uint32_t& r3, uint32_t a) {
    asm volatile("ldmatrix.sync.aligned.m8n8.x4.shared.b16 {%0,%1,%2,%3},[%4];"
                 : "=r"(r0), "=r"(r1), "=r"(r2), "=r"(r3) : "r"(a));
}

__global__ __launch_bounds__(256, 2) void gemm_hmma(
    const __half* __restrict__ A,   // [MTOT][CTXD]
    const __half* __restrict__ B,   // [HIDD][CTXD]  (W^T)
    float*        __restrict__ C)   // [MTOT][HIDD]
{
    extern __shared__ __half sm[];

    const int tid  = threadIdx.x;
    const int lane = tid & 31;
    const int warp = tid >> 5;      // 0..7
    const int wm   = warp & 3;      // 32-row M quarter
    const int wn   = warp >> 2;     // 64-col N half
    const int g    = lane >> 2;
    const int t4   = lane & 3;

    const int m0 = blockIdx.y * BM;
    const int n0 = blockIdx.x * BN;

    float acc[2][8][4];
#pragma unroll
    for (int i = 0; i < 2; i++)
#pragma unroll
        for (int j = 0; j < 8; j++)
#pragma unroll
            for (int r = 0; r < 4; r++) acc[i][j][r] = 0.f;

    auto load_chunk = [&](int buf, int kt) {
        __half* Asb = sm + buf * STAGE_H;
        __half* Bsb = Asb + TILE_H;
        const __half* Ag = A + (size_t)m0 * CTXD + kt * BK;
        const __half* Bg = B + (size_t)n0 * CTXD + kt * BK;
#pragma unroll
        for (int i = 0; i < 4; i++) {
            int idx = i * 256 + tid;
            int row = idx >> 3;
            int c8  = (idx & 7) * 8;
            cpasync16((uint32_t)__cvta_generic_to_shared(Asb + row * SSTRIDE + c8),
                      Ag + (size_t)row * CTXD + c8);
        }
#pragma unroll
        for (int i = 0; i < 4; i++) {
            int idx = i * 256 + tid;
            int row = idx >> 3;
            int c8  = (idx & 7) * 8;
            cpasync16((uint32_t)__cvta_generic_to_shared(Bsb + row * SSTRIDE + c8),
                      Bg + (size_t)row * CTXD + c8);
        }
        asm volatile("cp.async.commit_group;\n");
    };

    load_chunk(0, 0);
    load_chunk(1, 1);

    const int a_r  = lane & 15;
    const int a_k  = (lane >> 4) * 8;
    const int b_r  = lane & 7;
    const int b_no = ((lane >> 3) >> 1) * 8;
    const int b_ko = ((lane >> 3) & 1) * 8;

    for (int kt = 0; kt < NT; ++kt) {
        if (kt + 1 < NT) asm volatile("cp.async.wait_group 1;\n");
        else             asm volatile("cp.async.wait_group 0;\n");
        __syncthreads();
        if (kt + 2 < NT) load_chunk((kt + 2) % 3, kt + 2);

        const __half* Asb = sm + (kt % 3) * STAGE_H;
        const __half* Bsb = Asb + TILE_H;

#pragma unroll
        for (int ks = 0; ks < 4; ++ks) {
            const int k0 = ks * 16;

            uint32_t af[2][4];
#pragma unroll
            for (int mi = 0; mi < 2; ++mi) {
                uint32_t a = (uint32_t)__cvta_generic_to_shared(
                    Asb + (wm * 32 + mi * 16 + a_r) * SSTRIDE + k0 + a_k);
                ldsm_x4(af[mi][0], af[mi][1], af[mi][2], af[mi][3], a);
            }
            uint32_t bf[8][2];
#pragma unroll
            for (int nj = 0; nj < 4; ++nj) {
                uint32_t a = (uint32_t)__cvta_generic_to_shared(
                    Bsb + (wn * 64 + nj * 16 + b_no + b_r) * SSTRIDE + k0 + b_ko);
                ldsm_x4(bf[2 * nj][0], bf[2 * nj][1],
                        bf[2 * nj + 1][0], bf[2 * nj + 1][1], a);
            }
#pragma unroll
            for (int mi = 0; mi < 2; ++mi)
#pragma unroll
                for (int ni = 0; ni < 8; ++ni) {
                    asm volatile(
                        "mma.sync.aligned.m16n8k16.row.col.f32.f16.f16.f32 "
                        "{%0,%1,%2,%3},{%4,%5,%6,%7},{%8,%9},{%0,%1,%2,%3};\n"
                        : "+f"(acc[mi][ni][0]), "+f"(acc[mi][ni][1]),
                          "+f"(acc[mi][ni][2]), "+f"(acc[mi][ni][3])
                        : "r"(af[mi][0]), "r"(af[mi][1]),
                          "r"(af[mi][2]), "r"(af[mi][3]),
                          "r"(bf[ni][0]), "r"(bf[ni][1]));
                }
        }
        __syncthreads();
    }

    // epilogue
#pragma unroll
    for (int mi = 0; mi < 2; ++mi) {
#pragma unroll
        for (int ni = 0; ni < 8; ++ni) {
            const int r = m0 + wm * 32 + mi * 16 + g;
            const int c = n0 + wn * 64 + ni * 8 + t4 * 2;
            float2 v0 = make_float2(acc[mi][ni][0], acc[mi][ni][1]);
            float2 v1 = make_float2(acc[mi][ni][2], acc[mi][ni][3]);
            *reinterpret_cast<float2*>(C + (size_t)r * HIDD + c)       = v0;
            *reinterpret_cast<float2*>(C + (size_t)(r + 8) * HIDD + c) = v1;
        }
    }
}

// ---------------------------------------------------------------------------
extern "C" void kernel_launch(void* const* d_in, const int* in_sizes, int n_in,
                              void* d_out, int out_size) {
    const float* x      = (const float*)d_in[0];
    const float* W      = (const float*)d_in[1];
    const int*   nn_idx = (const int*)  d_in[2];
    const float* sim    = (const float*)d_in[3];
    float*       out    = (float*)d_out;

    __half* aggh = nullptr;
    __half* wh   = nullptr;
    cudaGetSymbolAddress((void**)&aggh, g_aggh);
    cudaGetSymbolAddress((void**)&wh,   g_Wh);

    cudaFuncSetAttribute(gemm_hmma,
                         cudaFuncAttributeMaxDynamicSharedMemorySize, GEMM_SMEM);

    prep_kernel<<<PREP_BLOCKS, 256>>>(x, nn_idx, sim, W);

    dim3 g2(HIDD / BN, MTOT / BM);   // (16, 256)
    gemm_hmma<<<g2, 256, GEMM_SMEM>>>(aggh, wh, out);
}